// round 1
// baseline (speedup 1.0000x reference)
#include <cuda_runtime.h>

#define TILE   32
#define NTAP   16
#define IN_H   1024
#define IN_W   1024
#define OUT_H  256
#define OUT_W  256
#define REG    (4*TILE + 12)   // 140: input span needed for 32 outputs
#define NTHREADS 256

// dynamic smem layout: s_in[REG][REG] then s_tmp[TILE][REG]
#define SMEM_FLOATS (REG*REG + TILE*REG)
#define SMEM_BYTES  (SMEM_FLOATS * 4)

__global__ __launch_bounds__(NTHREADS, 2)
void bicubic_imresize_kernel(const float* __restrict__ in, float* __restrict__ out)
{
    extern __shared__ float smem[];
    float* s_in  = smem;                 // [REG][REG]
    float* s_tmp = smem + REG * REG;     // [TILE][REG]

    const int img  = blockIdx.z;
    const int r0   = blockIdx.y * TILE;
    const int c0   = blockIdx.x * TILE;
    const int R0   = 4 * r0 - 6;         // first (unclamped) input row needed
    const int C0   = 4 * c0 - 6;         // first (unclamped) input col needed
    const int tid  = threadIdx.x;
    const int lane = tid & 31;
    const int warp = tid >> 5;

    // ---- 16-tap bicubic weights (same for every output position; see analysis) ----
    float w[NTAP];
    {
        float s = 0.f;
        #pragma unroll
        for (int j = 0; j < NTAP; ++j) {
            float a  = fabsf((7.5f - (float)j) * 0.25f);   // in (0, 2)
            float a2 = a * a, a3 = a2 * a;
            float v  = (a <= 1.f) ? (1.5f * a3 - 2.5f * a2 + 1.f)
                                  : (-0.5f * a3 + 2.5f * a2 - 4.f * a + 2.f);
            w[j] = v;
            s   += v;
        }
        const float inv = 1.f / s;
        #pragma unroll
        for (int j = 0; j < NTAP; ++j) w[j] *= inv;
    }

    const float* __restrict__ inp = in + (size_t)img * (IN_H * IN_W);

    // ---- stage 1: load clamped 140x140 input region into smem (coalesced) ----
    for (int i = warp; i < REG; i += 8) {
        const int gr = min(max(R0 + i, 0), IN_H - 1);
        const float* __restrict__ row = inp + (size_t)gr * IN_W;
        #pragma unroll
        for (int s = 0; s < 5; ++s) {
            const int j = lane + 32 * s;
            if (j < REG) {
                const int gc = min(max(C0 + j, 0), IN_W - 1);
                s_in[i * REG + j] = row[gc];
            }
        }
    }
    __syncthreads();

    // ---- stage 2: vertical 16-tap -> s_tmp[TILE][REG] ----
    #pragma unroll
    for (int t = 0; t < 4; ++t) {
        const int orow = warp + 8 * t;            // 0..31
        const float* __restrict__ colbase = s_in + (4 * orow) * REG;
        #pragma unroll
        for (int s = 0; s < 5; ++s) {
            const int j = lane + 32 * s;
            if (j < REG) {
                float acc = 0.f;
                #pragma unroll
                for (int k = 0; k < NTAP; ++k)
                    acc = fmaf(w[k], colbase[k * REG + j], acc);
                s_tmp[orow * REG + j] = acc;
            }
        }
    }
    __syncthreads();

    // ---- stage 3: horizontal 16-tap -> 32x32 output tile (coalesced store) ----
    float* __restrict__ outp = out + (size_t)img * (OUT_H * OUT_W);
    #pragma unroll
    for (int t = 0; t < 4; ++t) {
        const int orow = warp * 4 + t;            // 0..31
        const int oc   = lane;                    // 0..31
        const float* __restrict__ tr = s_tmp + orow * REG + 4 * oc;
        float acc = 0.f;
        #pragma unroll
        for (int k = 0; k < NTAP; ++k)
            acc = fmaf(w[k], tr[k], acc);
        outp[(size_t)(r0 + orow) * OUT_W + (c0 + oc)] = acc;
    }
}

extern "C" void kernel_launch(void* const* d_in, const int* in_sizes, int n_in,
                              void* d_out, int out_size)
{
    const float* in  = (const float*)d_in[0];
    float*       out = (float*)d_out;

    const int nimg = in_sizes[0] / (IN_H * IN_W);   // 8*3 = 24

    cudaFuncSetAttribute(bicubic_imresize_kernel,
                         cudaFuncAttributeMaxDynamicSharedMemorySize, SMEM_BYTES);

    dim3 grid(OUT_W / TILE, OUT_H / TILE, nimg);    // 8 x 8 x 24 = 1536 blocks
    bicubic_imresize_kernel<<<grid, NTHREADS, SMEM_BYTES>>>(in, out);
}

// round 2
// speedup vs baseline: 1.7022x; 1.7022x over previous
#include <cuda_runtime.h>

#define NTAP   16
#define IN_H   1024
#define IN_W   1024
#define OUT_H  256
#define OUT_W  256
#define MAXIMG 24

#define VCHUNK 8                    // output rows per thread (vertical pass)
#define VROWS  (4*VCHUNK + 12)      // 44 input rows feeding 8 outputs

// scratch: vertical-pass intermediate [img][orow][in_col]
__device__ float g_tmp[MAXIMG * OUT_H * IN_W];

__device__ __forceinline__ void make_weights(float* w) {
    float s = 0.f;
#pragma unroll
    for (int j = 0; j < NTAP; ++j) {
        float a  = fabsf((7.5f - (float)j) * 0.25f);
        float a2 = a * a, a3 = a2 * a;
        float v  = (a <= 1.f) ? (1.5f * a3 - 2.5f * a2 + 1.f)
                              : (-0.5f * a3 + 2.5f * a2 - 4.f * a + 2.f);
        w[j] = v;  s += v;
    }
    const float inv = 1.f / s;
#pragma unroll
    for (int j = 0; j < NTAP; ++j) w[j] *= inv;
}

// ---------------------------------------------------------------------------
// Pass 1: vertical 16-tap, stride 4.  Thread = (column, 8-output-row chunk).
// Zero smem, register accumulators, 44 coalesced dependence-free loads.
// ---------------------------------------------------------------------------
__global__ __launch_bounds__(256)
void bicubic_vpass(const float* __restrict__ in)
{
    const int col = blockIdx.x * 256 + threadIdx.x;     // 0..1023
    const int o0  = blockIdx.y * VCHUNK;                // first output row
    const int img = blockIdx.z;
    const int R0  = 4 * o0 - 6;                         // first input row tap

    float w[NTAP];
    make_weights(w);

    const float* __restrict__ inp = in + (size_t)img * (IN_H * IN_W);

    float acc[VCHUNK];
#pragma unroll
    for (int j = 0; j < VCHUNK; ++j) acc[j] = 0.f;

#pragma unroll
    for (int i = 0; i < VROWS; ++i) {
        const int gr = min(max(R0 + i, 0), IN_H - 1);
        const float v = __ldg(inp + (size_t)gr * IN_W + col);
#pragma unroll
        for (int j = 0; j < VCHUNK; ++j) {
            const int k = i - 4 * j;                    // tap index for output j
            if (k >= 0 && k < NTAP)                     // pruned at compile time
                acc[j] = fmaf(w[k], v, acc[j]);
        }
    }

    float* __restrict__ tmp = g_tmp + ((size_t)img * OUT_H + o0) * IN_W + col;
#pragma unroll
    for (int j = 0; j < VCHUNK; ++j)
        tmp[(size_t)j * IN_W] = acc[j];
}

// ---------------------------------------------------------------------------
// Pass 2: horizontal 16-tap, stride 4.  Block = one (img, output-row) strip.
// Stage clamped 1036-wide tmp row in smem, then 16 taps per output column.
// ---------------------------------------------------------------------------
#define HSPAN (4*OUT_W + 12)   // 1036

__global__ __launch_bounds__(256)
void bicubic_hpass(float* __restrict__ out)
{
    __shared__ float s[HSPAN];

    const int orow = blockIdx.x;
    const int img  = blockIdx.y;
    const int tid  = threadIdx.x;

    float w[NTAP];
    make_weights(w);

    const float* __restrict__ row = g_tmp + ((size_t)img * OUT_H + orow) * IN_W;

    // stage with border clamp: s[idx] = row[clamp(idx-6)]
#pragma unroll
    for (int t = 0; t < 5; ++t) {
        const int idx = tid + 256 * t;
        if (idx < HSPAN)
            s[idx] = row[min(max(idx - 6, 0), IN_W - 1)];
    }
    __syncthreads();

    const int ocol = tid;                               // 0..255
    const float* __restrict__ sp = s + 4 * ocol;        // == col 4*ocol-6+k
    float acc = 0.f;
#pragma unroll
    for (int k = 0; k < NTAP; ++k)
        acc = fmaf(w[k], sp[k], acc);

    out[((size_t)img * OUT_H + orow) * OUT_W + ocol] = acc;
}

extern "C" void kernel_launch(void* const* d_in, const int* in_sizes, int n_in,
                              void* d_out, int out_size)
{
    const float* in  = (const float*)d_in[0];
    float*       out = (float*)d_out;

    const int nimg = in_sizes[0] / (IN_H * IN_W);       // 24

    dim3 vgrid(IN_W / 256, OUT_H / VCHUNK, nimg);       // 4 x 32 x 24
    bicubic_vpass<<<vgrid, 256>>>(in);

    dim3 hgrid(OUT_H, nimg);                            // 256 x 24
    bicubic_hpass<<<hgrid, 256>>>(out);
}

// round 3
// speedup vs baseline: 2.0239x; 1.1890x over previous
#include <cuda_runtime.h>

#define IN_H   1024
#define IN_W   1024
#define OUT_H  256
#define OUT_W  256
#define MAXIMG 24
#define NTAP   16

#define VCHUNK 8
#define VROWS  (4*VCHUNK + 12)      // 44

// 16-tap bicubic weights for scale=0.25 (exact binary fractions, sum = 1).
// w[j] = cubic(|7.5-j|/4) / 4  — position-independent for this scale (see R0 analysis).
__device__ __constant__ const float W16[NTAP] = {
    -0.001708984375f, -0.010986328125f, -0.018310546875f, -0.011962890625f,
     0.022705078125f,  0.097412109375f,  0.181884765625f,  0.240966796875f,
     0.240966796875f,  0.181884765625f,  0.097412109375f,  0.022705078125f,
    -0.011962890625f, -0.018310546875f, -0.010986328125f, -0.001708984375f
};

// vertical-pass intermediate: [img][orow][in_col]
__device__ float g_tmp[MAXIMG * OUT_H * IN_W];

// ---------------------------------------------------------------------------
// Pass 1: vertical 16-tap, stride 4.  Thread = 4 columns (float4) x 8 output
// rows.  44 dependence-free LDG.128, register accumulators, zero smem.
// ---------------------------------------------------------------------------
__global__ __launch_bounds__(256)
void bicubic_vpass(const float* __restrict__ in)
{
    const int tid = threadIdx.x;                 // float4 column index 0..255
    const int o0  = blockIdx.x * VCHUNK;         // first output row of chunk
    const int img = blockIdx.y;
    const int R0  = 4 * o0 - 6;

    const float4* __restrict__ inp =
        (const float4*)(in + (size_t)img * (IN_H * IN_W));

    float4 acc[VCHUNK];
#pragma unroll
    for (int j = 0; j < VCHUNK; ++j) acc[j] = make_float4(0.f, 0.f, 0.f, 0.f);

#pragma unroll
    for (int i = 0; i < VROWS; ++i) {
        const int gr = min(max(R0 + i, 0), IN_H - 1);
        const float4 v = __ldg(inp + (size_t)gr * (IN_W / 4) + tid);
#pragma unroll
        for (int j = 0; j < VCHUNK; ++j) {
            const int k = i - 4 * j;             // tap index for output row j
            if (k >= 0 && k < NTAP) {
                const float wk = W16[k];
                acc[j].x = fmaf(wk, v.x, acc[j].x);
                acc[j].y = fmaf(wk, v.y, acc[j].y);
                acc[j].z = fmaf(wk, v.z, acc[j].z);
                acc[j].w = fmaf(wk, v.w, acc[j].w);
            }
        }
    }

    float4* __restrict__ tmp =
        (float4*)(g_tmp + ((size_t)img * OUT_H + o0) * IN_W) + tid;
#pragma unroll
    for (int j = 0; j < VCHUNK; ++j)
        tmp[(size_t)j * (IN_W / 4)] = acc[j];
}

// ---------------------------------------------------------------------------
// Pass 2: horizontal 16-tap, stride 4.  Block = one (img, output-row) strip.
// Stage row via LDG.128, read taps via 4 conflict-free LDS.128 per thread.
// ---------------------------------------------------------------------------
#define HSPAN (4*OUT_W + 12)   // 1036; pad to 1040 for alignment safety

__global__ __launch_bounds__(256)
void bicubic_hpass(float* __restrict__ out)
{
    __shared__ __align__(16) float s[1040];

    const int orow = blockIdx.x;
    const int img  = blockIdx.y;
    const int tid  = threadIdx.x;

    const float* __restrict__ row =
        g_tmp + ((size_t)img * OUT_H + orow) * IN_W;

    // interior: s[6 + 4t .. 6 + 4t+3] = row[4t .. 4t+3]  (vector load, scalar STS)
    {
        const float4 f = __ldg((const float4*)row + tid);
        float* d = s + 6 + 4 * tid;
        d[0] = f.x; d[1] = f.y; d[2] = f.z; d[3] = f.w;
    }
    // borders: s[0..5] = row[0], s[1030..1035] = row[1023]
    if (tid < 6) {
        s[tid]        = row[0];
        s[1030 + tid] = row[IN_W - 1];
    }
    __syncthreads();

    // taps for output ocol are s[4*ocol + 0 .. 15]: four aligned float4 reads
    const int ocol = tid;
    const float4* __restrict__ sv = (const float4*)s + ocol;
    const float4 v0 = sv[0], v1 = sv[1], v2 = sv[2], v3 = sv[3];

    float acc;
    acc = W16[0]  * v0.x;
    acc = fmaf(W16[1],  v0.y, acc);
    acc = fmaf(W16[2],  v0.z, acc);
    acc = fmaf(W16[3],  v0.w, acc);
    acc = fmaf(W16[4],  v1.x, acc);
    acc = fmaf(W16[5],  v1.y, acc);
    acc = fmaf(W16[6],  v1.z, acc);
    acc = fmaf(W16[7],  v1.w, acc);
    acc = fmaf(W16[8],  v2.x, acc);
    acc = fmaf(W16[9],  v2.y, acc);
    acc = fmaf(W16[10], v2.z, acc);
    acc = fmaf(W16[11], v2.w, acc);
    acc = fmaf(W16[12], v3.x, acc);
    acc = fmaf(W16[13], v3.y, acc);
    acc = fmaf(W16[14], v3.z, acc);
    acc = fmaf(W16[15], v3.w, acc);

    out[((size_t)img * OUT_H + orow) * OUT_W + ocol] = acc;
}

extern "C" void kernel_launch(void* const* d_in, const int* in_sizes, int n_in,
                              void* d_out, int out_size)
{
    const float* in  = (const float*)d_in[0];
    float*       out = (float*)d_out;

    const int nimg = in_sizes[0] / (IN_H * IN_W);      // 24

    dim3 vgrid(OUT_H / VCHUNK, nimg);                  // 32 x 24 = 768 blocks
    bicubic_vpass<<<vgrid, 256>>>(in);

    dim3 hgrid(OUT_H, nimg);                           // 256 x 24 = 6144 blocks
    bicubic_hpass<<<hgrid, 256>>>(out);
}

// round 4
// speedup vs baseline: 3.3679x; 1.6641x over previous
#include <cuda_runtime.h>

#define IN_H   1024
#define IN_W   1024
#define OUT_H  256
#define OUT_W  256
#define NTAP   16

#define VCHUNK 8
#define VROWS  (4*VCHUNK + 12)      // 44 input rows feed 8 output rows

// ---------------------------------------------------------------------------
// Fully fused separable bicubic 4x downsample.
// Block = (img, 8 output rows) strip, full 1024-col width, 256 threads.
//   Phase V: thread owns 4 cols (float4); 44 dependence-free LDG.128,
//            16-tap stride-4 vertical filter into 8 float4 register accs.
//   Dump to smem (8 x 1024 floats = 32 KB) via conflict-free STS.128.
//   Phase H: 16-tap stride-4 horizontal from smem; taps [4*oc-6 .. 4*oc+9]
//            = elements 2..17 of five aligned float4s (conflict-free LDS.128).
// ---------------------------------------------------------------------------
__global__ __launch_bounds__(256)
void bicubic_fused(const float* __restrict__ in, float* __restrict__ out)
{
    // 16-tap weights for scale=0.25 (exact binary fractions; fold to immediates)
    constexpr float W[NTAP] = {
        -0.001708984375f, -0.010986328125f, -0.018310546875f, -0.011962890625f,
         0.022705078125f,  0.097412109375f,  0.181884765625f,  0.240966796875f,
         0.240966796875f,  0.181884765625f,  0.097412109375f,  0.022705078125f,
        -0.011962890625f, -0.018310546875f, -0.010986328125f, -0.001708984375f };

    __shared__ __align__(16) float s[VCHUNK][IN_W];   // 32 KB

    const int tid = threadIdx.x;                 // float4-column 0..255
    const int o0  = blockIdx.x * VCHUNK;         // first output row
    const int img = blockIdx.y;
    const int R0  = 4 * o0 - 6;

    const float4* __restrict__ inp =
        (const float4*)(in + (size_t)img * (IN_H * IN_W));

    // ---- Phase V: vertical 16-tap into registers ----
    float4 acc[VCHUNK];
#pragma unroll
    for (int j = 0; j < VCHUNK; ++j) acc[j] = make_float4(0.f, 0.f, 0.f, 0.f);

#pragma unroll
    for (int i = 0; i < VROWS; ++i) {
        const int gr = min(max(R0 + i, 0), IN_H - 1);
        const float4 v = __ldg(inp + (size_t)gr * (IN_W / 4) + tid);
#pragma unroll
        for (int j = 0; j < VCHUNK; ++j) {
            const int k = i - 4 * j;             // tap index for output row j
            if (k >= 0 && k < NTAP) {            // compile-time pruned
                acc[j].x = fmaf(W[k], v.x, acc[j].x);
                acc[j].y = fmaf(W[k], v.y, acc[j].y);
                acc[j].z = fmaf(W[k], v.z, acc[j].z);
                acc[j].w = fmaf(W[k], v.w, acc[j].w);
            }
        }
    }

    // ---- dump strip to smem: STS.128, conflict-free ----
#pragma unroll
    for (int j = 0; j < VCHUNK; ++j)
        ((float4*)s[j])[tid] = acc[j];
    __syncthreads();

    // ---- Phase H: horizontal 16-tap, one output column per thread ----
    const int oc = tid;
    float* __restrict__ outp = out + ((size_t)img * OUT_H + o0) * OUT_W + oc;

#pragma unroll
    for (int j = 0; j < VCHUNK; ++j) {
        const float* __restrict__ srow = s[j];
        float r;
        if (oc >= 2 && oc <= 253) {
            const float4* __restrict__ sv = (const float4*)srow;
            const float4 a = sv[oc - 2];   // s[4oc-8 .. 4oc-5]
            const float4 b = sv[oc - 1];
            const float4 c = sv[oc];
            const float4 d = sv[oc + 1];
            const float4 e = sv[oc + 2];   // s[4oc+8 .. 4oc+11]
            r = W[0] * a.z;                // tap 0 = s[4oc-6]
            r = fmaf(W[1],  a.w, r);
            r = fmaf(W[2],  b.x, r);
            r = fmaf(W[3],  b.y, r);
            r = fmaf(W[4],  b.z, r);
            r = fmaf(W[5],  b.w, r);
            r = fmaf(W[6],  c.x, r);
            r = fmaf(W[7],  c.y, r);
            r = fmaf(W[8],  c.z, r);
            r = fmaf(W[9],  c.w, r);
            r = fmaf(W[10], d.x, r);
            r = fmaf(W[11], d.y, r);
            r = fmaf(W[12], d.z, r);
            r = fmaf(W[13], d.w, r);
            r = fmaf(W[14], e.x, r);
            r = fmaf(W[15], e.y, r);       // tap 15 = s[4oc+9]
        } else {
            // edge lanes (oc in {0,1,254,255}): clamped scalar taps
            r = 0.f;
#pragma unroll
            for (int k = 0; k < NTAP; ++k)
                r = fmaf(W[k], srow[min(max(4 * oc - 6 + k, 0), IN_W - 1)], r);
        }
        outp[(size_t)j * OUT_W] = r;
    }
}

extern "C" void kernel_launch(void* const* d_in, const int* in_sizes, int n_in,
                              void* d_out, int out_size)
{
    const float* in  = (const float*)d_in[0];
    float*       out = (float*)d_out;

    const int nimg = in_sizes[0] / (IN_H * IN_W);       // 24

    dim3 grid(OUT_H / VCHUNK, nimg);                    // 32 x 24 = 768 blocks
    bicubic_fused<<<grid, 256>>>(in, out);
}